// round 13
// baseline (speedup 1.0000x reference)
#include <cuda_runtime.h>
#include <cuda_bf16.h>
#include <math.h>

#define NN 100000
#define NE 20000
#define NP 3200000
#define D  512
#define NREP 4                    // edge accumulator replicas

// ---------------- scratch (device globals; no allocation) ----------------
__device__ float4 g_m[NN];            // gelu(x @ Wmsg^T)         [N,4]
__device__ float4 g_u[NN];            // x @ Wupd^T + b           [N,4]
__device__ float4 g_ef[NE];           // edge means

// zero-initialized accumulators, packed so ONE memset clears them all (3.6MB)
struct Scratch {
    float4 esum[NREP * NE];           // 1.28 MB
    float  ecnt[NREP * NE];           // 0.32 MB
    float4 nsum[NN];                  // 1.6 MB
    float  ncnt[NN];                  // 0.4 MB
};
__device__ Scratch g_s;

__device__ __forceinline__ float gelu_exact(float v) {
    return 0.5f * v * (1.0f + erff(v * 0.70710678118654752f));
}

// ---------------- packed f32x2 helpers (sm_100a) ----------------
__device__ __forceinline__ unsigned long long pk2(float a, float b) {
    unsigned long long r;
    asm("mov.b64 %0, {%1, %2};" : "=l"(r) : "f"(a), "f"(b));
    return r;
}
__device__ __forceinline__ void fma2(unsigned long long& d,
                                     unsigned long long a,
                                     unsigned long long b) {
    asm("fma.rn.f32x2 %0, %1, %2, %0;" : "+l"(d) : "l"(a), "l"(b));
}
__device__ __forceinline__ float upk_sum(unsigned long long v) {
    float x, y;
    asm("mov.b64 {%0, %1}, %2;" : "=f"(x), "=f"(y) : "l"(v));
    return x + y;
}

// ---------------- kernel 1: fused dual GEMV + GELU + balanced pair counting ----------------
// R10-proven shape: 6250 blocks x 256; each warp = 2 rows x 8 features, f32x2.
// After the GEMV stores, the kernel fires the PDL trigger so k_scatter_edges
// launches and overlaps Phase B's count atomics (disjoint write sets:
// esum vs ecnt/ncnt; g_m visibility guaranteed by trigger/grid-sync pairing).
__global__ __launch_bounds__(256) void k_linear(
    const float4* __restrict__ x4,      // [N, 128] float4
    const float4* __restrict__ wmsg4,   // [4, 128]
    const float4* __restrict__ wupd4,   // [4, 128]
    const float*  __restrict__ b_upd,   // [4]
    const int2*   __restrict__ pn2,
    const int2*   __restrict__ pe2)
{
    __shared__ float4 sW[8 * 128];
    __shared__ float  sB[4];

    int t = threadIdx.x;
    for (int i = t; i < 4 * 128; i += 256) sW[i] = wmsg4[i];
    for (int i = t; i < 4 * 128; i += 256) sW[4 * 128 + i] = wupd4[i];
    if (t < 4) sB[t] = b_upd[t];
    __syncthreads();

    int warp = t >> 5;
    int lane = t & 31;
    int row0 = (blockIdx.x * 8 + warp) * 2;   // 6250 blocks * 16 rows = 100000

    unsigned long long acc2[2][8];
    #pragma unroll
    for (int r = 0; r < 2; r++)
        #pragma unroll
        for (int k = 0; k < 8; k++) acc2[r][k] = 0ull;

    #pragma unroll
    for (int i = 0; i < 4; i++) {
        int c = i * 32 + lane;                // float4 column index 0..127
        unsigned long long wlo[8], whi[8];
        #pragma unroll
        for (int k = 0; k < 8; k++) {
            float4 wv = sW[k * 128 + c];
            wlo[k] = pk2(wv.x, wv.y);
            whi[k] = pk2(wv.z, wv.w);
        }
        #pragma unroll
        for (int r = 0; r < 2; r++) {
            float4 xv = x4[(size_t)(row0 + r) * 128 + c];
            unsigned long long xlo = pk2(xv.x, xv.y);
            unsigned long long xhi = pk2(xv.z, xv.w);
            #pragma unroll
            for (int k = 0; k < 8; k++) {
                fma2(acc2[r][k], xlo, wlo[k]);
                fma2(acc2[r][k], xhi, whi[k]);
            }
        }
    }

    float acc[2][8];
    #pragma unroll
    for (int r = 0; r < 2; r++)
        #pragma unroll
        for (int k = 0; k < 8; k++) {
            float s = upk_sum(acc2[r][k]);
            #pragma unroll
            for (int off = 16; off > 0; off >>= 1)
                s += __shfl_xor_sync(0xFFFFFFFFu, s, off);
            acc[r][k] = s;
        }

    if (lane < 2) {
        int row = row0 + lane;
        float4 mv;
        mv.x = gelu_exact(acc[lane][0]);
        mv.y = gelu_exact(acc[lane][1]);
        mv.z = gelu_exact(acc[lane][2]);
        mv.w = gelu_exact(acc[lane][3]);
        g_m[row] = mv;
        float4 uv;
        uv.x = acc[lane][4] + sB[0];
        uv.y = acc[lane][5] + sB[1];
        uv.z = acc[lane][6] + sB[2];
        uv.w = acc[lane][7] + sB[3];
        g_u[row] = uv;
    }

    // PDL early trigger: g_m/g_u written -> successor (k_scatter_edges) may
    // launch now and overlap the count phase below.
    cudaTriggerProgrammaticLaunchCompletion();

    // ---- Phase B: multiplicity counts, one int2 chunk per thread ----
    cudaGridDependencySynchronize();          // scratch memset must be done
    int tid = blockIdx.x * 256 + t;           // [0, 1.6M) == NP/2 chunks
    int2 n2 = __ldg(&pn2[tid]);
    int2 e2 = __ldg(&pe2[tid]);
    int erep = (t & (NREP - 1)) * NE;
    atomicAdd(&g_s.ecnt[erep + e2.x], 1.0f);
    atomicAdd(&g_s.ncnt[n2.x], 1.0f);
    atomicAdd(&g_s.ecnt[erep + e2.y], 1.0f);
    atomicAdd(&g_s.ncnt[n2.y], 1.0f);
}

// ---------------- kernel 2: pair scatter #1 (node msgs -> edge sums) ----------------
// PDL: launches on k_linear's early trigger; index loads run before the
// dependency sync; esum REDs overlap k_linear's count tail (disjoint arrays).
__global__ __launch_bounds__(256) void k_scatter_edges(
    const int4* __restrict__ pn4,
    const int4* __restrict__ pe4)
{
    int t = blockIdx.x * blockDim.x + threadIdx.x;
    int4 n4 = __ldg(&pn4[t]);
    int4 e4 = __ldg(&pe4[t]);
    int erep = (threadIdx.x & (NREP - 1)) * NE;

    cudaGridDependencySynchronize();          // wait: g_m ready (trigger fired)

    #pragma unroll
    for (int j = 0; j < 4; j++) {
        int n = (j == 0) ? n4.x : (j == 1) ? n4.y : (j == 2) ? n4.z : n4.w;
        int e = (j == 0) ? e4.x : (j == 1) ? e4.y : (j == 2) ? e4.z : e4.w;
        float4 mv = g_m[n];
        atomicAdd(&g_s.esum[erep + e], mv);      // RED.128 (only atomic here)
    }
}

// ---------------- kernel 3: edge mean — 4 threads per edge ----------------
// REGULAR stream launch (no PDL): acts as a full barrier so it cannot start
// before BOTH k_linear (ecnt writers) and k_scatter_edges (esum writers) end.
__global__ void k_edge_mean() {
    int gid = blockIdx.x * blockDim.x + threadIdx.x;
    int e = gid >> 2;                         // edge
    int r = gid & 3;                          // replica
    if (e >= NE) return;
    float4 v = g_s.esum[r * NE + e];
    float cnt = g_s.ecnt[r * NE + e];
    #pragma unroll
    for (int off = 2; off > 0; off >>= 1) {
        v.x += __shfl_xor_sync(0xFFFFFFFFu, v.x, off);
        v.y += __shfl_xor_sync(0xFFFFFFFFu, v.y, off);
        v.z += __shfl_xor_sync(0xFFFFFFFFu, v.z, off);
        v.w += __shfl_xor_sync(0xFFFFFFFFu, v.w, off);
        cnt += __shfl_xor_sync(0xFFFFFFFFu, cnt, off);
    }
    if (r == 0) {
        float inv = 1.0f / fmaxf(cnt, 1.0f);
        g_ef[e] = make_float4(v.x * inv, v.y * inv, v.z * inv, v.w * inv);
    }
}

// ---------------- kernel 4: pair scatter #2 (edge means -> node sums) ----------------
__global__ __launch_bounds__(256) void k_scatter_nodes(
    const int4* __restrict__ pn4,
    const int4* __restrict__ pe4)
{
    int t = blockIdx.x * blockDim.x + threadIdx.x;
    int4 n4 = __ldg(&pn4[t]);
    int4 e4 = __ldg(&pe4[t]);

    cudaGridDependencySynchronize();          // wait: g_ef ready

    #pragma unroll
    for (int j = 0; j < 4; j++) {
        int n = (j == 0) ? n4.x : (j == 1) ? n4.y : (j == 2) ? n4.z : n4.w;
        int e = (j == 0) ? e4.x : (j == 1) ? e4.y : (j == 2) ? e4.z : e4.w;
        float4 ev = g_ef[e];
        atomicAdd(&g_s.nsum[n], ev);             // RED.128 (only atomic here)
    }
}

// ---------------- kernel 5: update + log_softmax ----------------
__global__ void k_final(float4* __restrict__ out4) {
    cudaGridDependencySynchronize();          // launch-latency hiding only
    int i = blockIdx.x * blockDim.x + threadIdx.x;
    if (i >= NN) return;
    float4 u = g_u[i];
    float4 s = g_s.nsum[i];
    float inv = 1.0f / fmaxf(g_s.ncnt[i], 1.0f);
    float h0 = gelu_exact(u.x + s.x * inv);
    float h1 = gelu_exact(u.y + s.y * inv);
    float h2 = gelu_exact(u.z + s.z * inv);
    float h3 = gelu_exact(u.w + s.w * inv);
    float mx = fmaxf(fmaxf(h0, h1), fmaxf(h2, h3));
    float lse = mx + logf(expf(h0 - mx) + expf(h1 - mx)
                        + expf(h2 - mx) + expf(h3 - mx));
    out4[i] = make_float4(h0 - lse, h1 - lse, h2 - lse, h3 - lse);
}

// ---------------- PDL launch helper ----------------
template <typename K, typename... Args>
static void launch_pdl(K kernel, dim3 grid, dim3 block, Args... args) {
    cudaLaunchConfig_t cfg = {};
    cfg.gridDim = grid;
    cfg.blockDim = block;
    cfg.dynamicSmemBytes = 0;
    cfg.stream = 0;
    cudaLaunchAttribute attr[1];
    attr[0].id = cudaLaunchAttributeProgrammaticStreamSerialization;
    attr[0].val.programmaticStreamSerializationAllowed = 1;
    cfg.attrs = attr;
    cfg.numAttrs = 1;
    cudaLaunchKernelEx(&cfg, kernel, args...);
}

// ---------------- launch ----------------
extern "C" void kernel_launch(void* const* d_in, const int* in_sizes, int n_in,
                              void* d_out, int out_size) {
    const float* x         = (const float*)d_in[0];
    const int*   pair_node = (const int*)d_in[1];
    const int*   pair_edge = (const int*)d_in[2];
    const float* W_msg     = (const float*)d_in[3];
    const float* W_upd     = (const float*)d_in[4];
    const float* b_upd     = (const float*)d_in[5];
    float4* out4 = (float4*)d_out;

    static void* scratch_ptr = nullptr;
    if (!scratch_ptr) cudaGetSymbolAddress(&scratch_ptr, g_s);
    cudaMemsetAsync(scratch_ptr, 0, sizeof(Scratch));

    launch_pdl(k_linear, dim3(NN / 16), dim3(256),
               (const float4*)x, (const float4*)W_msg, (const float4*)W_upd,
               b_upd, (const int2*)pair_node, (const int2*)pair_edge);

    // launches on k_linear's explicit trigger (after GEMV, before counts)
    launch_pdl(k_scatter_edges, dim3(NP / 4 / 256), dim3(256),
               (const int4*)pair_node, (const int4*)pair_edge);

    // REGULAR launch: full barrier vs k_linear's count tail AND scatter_edges
    k_edge_mean<<<(NE * 4 + 255) / 256, 256>>>();

    launch_pdl(k_scatter_nodes, dim3(NP / 4 / 256), dim3(256),
               (const int4*)pair_node, (const int4*)pair_edge);

    launch_pdl(k_final, dim3((NN + 255) / 256), dim3(256), out4);
}

// round 14
// speedup vs baseline: 1.0154x; 1.0154x over previous
#include <cuda_runtime.h>
#include <cuda_bf16.h>
#include <math.h>

#define NN 100000
#define NE 20000
#define NP 3200000
#define D  512
#define NREP 4                    // edge accumulator replicas

// ---------------- scratch (device globals; no allocation) ----------------
__device__ float4 g_m[NN];            // gelu(x @ Wmsg^T)         [N,4]
__device__ float4 g_u[NN];            // x @ Wupd^T + b           [N,4]
__device__ float4 g_ef[NE];           // edge means

// zero-initialized accumulators, packed so ONE memset clears them all (3.6MB)
struct Scratch {
    float4 esum[NREP * NE];           // 1.28 MB
    float  ecnt[NREP * NE];           // 0.32 MB
    float4 nsum[NN];                  // 1.6 MB
    float  ncnt[NN];                  // 0.4 MB
};
__device__ Scratch g_s;

__device__ __forceinline__ float gelu_exact(float v) {
    return 0.5f * v * (1.0f + erff(v * 0.70710678118654752f));
}

// ---------------- packed f32x2 helpers (sm_100a) ----------------
__device__ __forceinline__ unsigned long long pk2(float a, float b) {
    unsigned long long r;
    asm("mov.b64 %0, {%1, %2};" : "=l"(r) : "f"(a), "f"(b));
    return r;
}
__device__ __forceinline__ void fma2(unsigned long long& d,
                                     unsigned long long a,
                                     unsigned long long b) {
    asm("fma.rn.f32x2 %0, %1, %2, %0;" : "+l"(d) : "l"(a), "l"(b));
}
__device__ __forceinline__ float upk_sum(unsigned long long v) {
    float x, y;
    asm("mov.b64 {%0, %1}, %2;" : "=f"(x), "=f"(y) : "l"(v));
    return x + y;
}

// ---------------- kernel 1: fused dual GEMV + GELU + balanced pair counting ----------------
// 6250 blocks x 128 threads (4 warps). Each warp = 4 rows x 8 features with
// f32x2 FMA: same FMA count as the 2-row form but HALF the smem W traffic
// (W loads amortize over 4 rows). ~130 regs/thread -> 128-thread blocks keep
// 3 CTAs/SM (12 warps, enough LDG in flight to saturate DRAM).
// Phase B: exactly one int4 pair chunk per thread (6250*128 = NP/4).
__global__ __launch_bounds__(128) void k_linear(
    const float4* __restrict__ x4,      // [N, 128] float4
    const float4* __restrict__ wmsg4,   // [4, 128]
    const float4* __restrict__ wupd4,   // [4, 128]
    const float*  __restrict__ b_upd,   // [4]
    const int4*   __restrict__ pn4,
    const int4*   __restrict__ pe4)
{
    __shared__ float4 sW[8 * 128];
    __shared__ float  sB[4];

    int t = threadIdx.x;
    for (int i = t; i < 4 * 128; i += 128) sW[i] = wmsg4[i];
    for (int i = t; i < 4 * 128; i += 128) sW[4 * 128 + i] = wupd4[i];
    if (t < 4) sB[t] = b_upd[t];
    __syncthreads();

    int warp = t >> 5;
    int lane = t & 31;
    int row0 = (blockIdx.x * 4 + warp) * 4;   // 6250 blocks * 16 rows = 100000

    unsigned long long acc2[4][8];
    #pragma unroll
    for (int r = 0; r < 4; r++)
        #pragma unroll
        for (int k = 0; k < 8; k++) acc2[r][k] = 0ull;

    #pragma unroll
    for (int i = 0; i < 4; i++) {
        int c = i * 32 + lane;                // float4 column index 0..127
        unsigned long long wlo[8], whi[8];
        #pragma unroll
        for (int k = 0; k < 8; k++) {
            float4 wv = sW[k * 128 + c];
            wlo[k] = pk2(wv.x, wv.y);
            whi[k] = pk2(wv.z, wv.w);
        }
        #pragma unroll
        for (int r = 0; r < 4; r++) {
            float4 xv = x4[(size_t)(row0 + r) * 128 + c];
            unsigned long long xlo = pk2(xv.x, xv.y);
            unsigned long long xhi = pk2(xv.z, xv.w);
            #pragma unroll
            for (int k = 0; k < 8; k++) {
                fma2(acc2[r][k], xlo, wlo[k]);
                fma2(acc2[r][k], xhi, whi[k]);
            }
        }
    }

    // collapse packed halves, butterfly reduce across the warp
    float acc[4][8];
    #pragma unroll
    for (int r = 0; r < 4; r++)
        #pragma unroll
        for (int k = 0; k < 8; k++) {
            float s = upk_sum(acc2[r][k]);
            #pragma unroll
            for (int off = 16; off > 0; off >>= 1)
                s += __shfl_xor_sync(0xFFFFFFFFu, s, off);
            acc[r][k] = s;
        }

    if (lane < 4) {
        int row = row0 + lane;
        float4 mv;
        mv.x = gelu_exact(acc[lane][0]);
        mv.y = gelu_exact(acc[lane][1]);
        mv.z = gelu_exact(acc[lane][2]);
        mv.w = gelu_exact(acc[lane][3]);
        g_m[row] = mv;
        float4 uv;
        uv.x = acc[lane][4] + sB[0];
        uv.y = acc[lane][5] + sB[1];
        uv.z = acc[lane][6] + sB[2];
        uv.w = acc[lane][7] + sB[3];
        g_u[row] = uv;
    }

    // ---- Phase B: multiplicity counts, exactly one int4 chunk per thread ----
    cudaGridDependencySynchronize();          // scratch memset must be done
    int tid = blockIdx.x * 128 + t;           // 6250*128 = 800000 = NP/4
    int4 n4 = __ldg(&pn4[tid]);
    int4 e4 = __ldg(&pe4[tid]);
    int erep = (t & (NREP - 1)) * NE;
    #pragma unroll
    for (int j = 0; j < 4; j++) {
        int n = (j == 0) ? n4.x : (j == 1) ? n4.y : (j == 2) ? n4.z : n4.w;
        int e = (j == 0) ? e4.x : (j == 1) ? e4.y : (j == 2) ? e4.z : e4.w;
        atomicAdd(&g_s.ecnt[erep + e], 1.0f);
        atomicAdd(&g_s.ncnt[n], 1.0f);
    }
}

// ---------------- kernel 2: pair scatter #1 (node msgs -> edge sums) ----------------
// PDL: index loads (pure inputs) run BEFORE the grid dependency sync.
__global__ __launch_bounds__(256) void k_scatter_edges(
    const int4* __restrict__ pn4,
    const int4* __restrict__ pe4)
{
    int t = blockIdx.x * blockDim.x + threadIdx.x;
    int4 n4 = __ldg(&pn4[t]);
    int4 e4 = __ldg(&pe4[t]);
    int erep = (threadIdx.x & (NREP - 1)) * NE;

    cudaGridDependencySynchronize();          // wait: g_m ready

    #pragma unroll
    for (int j = 0; j < 4; j++) {
        int n = (j == 0) ? n4.x : (j == 1) ? n4.y : (j == 2) ? n4.z : n4.w;
        int e = (j == 0) ? e4.x : (j == 1) ? e4.y : (j == 2) ? e4.z : e4.w;
        float4 mv = g_m[n];
        atomicAdd(&g_s.esum[erep + e], mv);      // RED.128 (only atomic here)
    }
}

// ---------------- kernel 3: edge mean — 4 threads per edge ----------------
__global__ void k_edge_mean() {
    cudaGridDependencySynchronize();          // launch-latency hiding only
    int gid = blockIdx.x * blockDim.x + threadIdx.x;
    int e = gid >> 2;                         // edge
    int r = gid & 3;                          // replica
    if (e >= NE) return;
    float4 v = g_s.esum[r * NE + e];
    float cnt = g_s.ecnt[r * NE + e];
    #pragma unroll
    for (int off = 2; off > 0; off >>= 1) {
        v.x += __shfl_xor_sync(0xFFFFFFFFu, v.x, off);
        v.y += __shfl_xor_sync(0xFFFFFFFFu, v.y, off);
        v.z += __shfl_xor_sync(0xFFFFFFFFu, v.z, off);
        v.w += __shfl_xor_sync(0xFFFFFFFFu, v.w, off);
        cnt += __shfl_xor_sync(0xFFFFFFFFu, cnt, off);
    }
    if (r == 0) {
        float inv = 1.0f / fmaxf(cnt, 1.0f);
        g_ef[e] = make_float4(v.x * inv, v.y * inv, v.z * inv, v.w * inv);
    }
}

// ---------------- kernel 4: pair scatter #2 (edge means -> node sums) ----------------
__global__ __launch_bounds__(256) void k_scatter_nodes(
    const int4* __restrict__ pn4,
    const int4* __restrict__ pe4)
{
    int t = blockIdx.x * blockDim.x + threadIdx.x;
    int4 n4 = __ldg(&pn4[t]);
    int4 e4 = __ldg(&pe4[t]);

    cudaGridDependencySynchronize();          // wait: g_ef ready

    #pragma unroll
    for (int j = 0; j < 4; j++) {
        int n = (j == 0) ? n4.x : (j == 1) ? n4.y : (j == 2) ? n4.z : n4.w;
        int e = (j == 0) ? e4.x : (j == 1) ? e4.y : (j == 2) ? e4.z : e4.w;
        float4 ev = g_ef[e];
        atomicAdd(&g_s.nsum[n], ev);             // RED.128 (only atomic here)
    }
}

// ---------------- kernel 5: update + log_softmax ----------------
__global__ void k_final(float4* __restrict__ out4) {
    cudaGridDependencySynchronize();          // launch-latency hiding only
    int i = blockIdx.x * blockDim.x + threadIdx.x;
    if (i >= NN) return;
    float4 u = g_u[i];
    float4 s = g_s.nsum[i];
    float inv = 1.0f / fmaxf(g_s.ncnt[i], 1.0f);
    float h0 = gelu_exact(u.x + s.x * inv);
    float h1 = gelu_exact(u.y + s.y * inv);
    float h2 = gelu_exact(u.z + s.z * inv);
    float h3 = gelu_exact(u.w + s.w * inv);
    float mx = fmaxf(fmaxf(h0, h1), fmaxf(h2, h3));
    float lse = mx + logf(expf(h0 - mx) + expf(h1 - mx)
                        + expf(h2 - mx) + expf(h3 - mx));
    out4[i] = make_float4(h0 - lse, h1 - lse, h2 - lse, h3 - lse);
}

// ---------------- PDL launch helper ----------------
template <typename K, typename... Args>
static void launch_pdl(K kernel, dim3 grid, dim3 block, Args... args) {
    cudaLaunchConfig_t cfg = {};
    cfg.gridDim = grid;
    cfg.blockDim = block;
    cfg.dynamicSmemBytes = 0;
    cfg.stream = 0;
    cudaLaunchAttribute attr[1];
    attr[0].id = cudaLaunchAttributeProgrammaticStreamSerialization;
    attr[0].val.programmaticStreamSerializationAllowed = 1;
    cfg.attrs = attr;
    cfg.numAttrs = 1;
    cudaLaunchKernelEx(&cfg, kernel, args...);
}

// ---------------- launch ----------------
extern "C" void kernel_launch(void* const* d_in, const int* in_sizes, int n_in,
                              void* d_out, int out_size) {
    const float* x         = (const float*)d_in[0];
    const int*   pair_node = (const int*)d_in[1];
    const int*   pair_edge = (const int*)d_in[2];
    const float* W_msg     = (const float*)d_in[3];
    const float* W_upd     = (const float*)d_in[4];
    const float* b_upd     = (const float*)d_in[5];
    float4* out4 = (float4*)d_out;

    static void* scratch_ptr = nullptr;
    if (!scratch_ptr) cudaGetSymbolAddress(&scratch_ptr, g_s);
    cudaMemsetAsync(scratch_ptr, 0, sizeof(Scratch));

    launch_pdl(k_linear, dim3(NN / 16), dim3(128),
               (const float4*)x, (const float4*)W_msg, (const float4*)W_upd,
               b_upd, (const int4*)pair_node, (const int4*)pair_edge);

    launch_pdl(k_scatter_edges, dim3(NP / 4 / 256), dim3(256),
               (const int4*)pair_node, (const int4*)pair_edge);

    launch_pdl(k_edge_mean, dim3((NE * 4 + 255) / 256), dim3(256));

    launch_pdl(k_scatter_nodes, dim3(NP / 4 / 256), dim3(256),
               (const int4*)pair_node, (const int4*)pair_edge);

    launch_pdl(k_final, dim3((NN + 255) / 256), dim3(256), out4);
}